// round 14
// baseline (speedup 1.0000x reference)
#include <cuda_runtime.h>
#include <cuda_fp16.h>
#include <cstdint>

// ---------------------------------------------------------------------------
// Problem constants
// ---------------------------------------------------------------------------
constexpr int kN    = 512;
constexpr int kBZ   = 32;
constexpr int kTC   = 256;
constexpr int kF1   = 256;
constexpr int kF2   = 128;
constexpr int kE    = 524288;
constexpr int kNTOT = kBZ * kN;          // 16384
constexpr int kKTOT = kF2 * 2 * kN;      // 131072

// ---------------------------------------------------------------------------
// Scratch (offsets in floats)
// ---------------------------------------------------------------------------
constexpr long OFF_EG   = 0;
constexpr long OFF_FG   = OFF_EG   + (long)kNTOT;
constexpr long OFF_A8   = OFF_FG   + (long)kNTOT;                // u8 view
constexpr long OFF_DISD = OFF_A8   + (long)kBZ * kN * kN / 4;
constexpr long OFF_PART = OFF_DISD + (long)kNTOT;                // 32*8*512
constexpr long OFF_H    = OFF_PART + (long)kBZ * 8 * kN;
constexpr long OFF_SC1  = OFF_H    + (long)kNTOT * kF1;
constexpr long OFF_XW2  = OFF_SC1  + (long)kNTOT * kF1;
constexpr long OFF_EMB  = OFF_XW2  + (long)kNTOT * kF2;
constexpr long OFF_DISS = OFF_EMB  + (long)kNTOT * 256;
constexpr long OFF_DEGS = OFF_DISS + (long)kNTOT;                // int
constexpr long OFF_H1   = OFF_DEGS + (long)kNTOT;
constexpr long OFF_NS   = OFF_H1   + (long)kBZ * 256;            // int, kNTOT+1
constexpr long OFF_CUR  = OFF_NS   + (long)kNTOT + 4;            // int
constexpr long OFF_ESRC = OFF_CUR  + (long)kNTOT;                // int, kE
constexpr long OFF_XW1H = OFF_ESRC + (long)kE;                   // half, NTOT*F1
constexpr long OFF_XWS2H= OFF_XW1H + (long)kNTOT * kF1 / 2;      // half, NTOT*F2
constexpr long SCRATCH_FLOATS = OFF_XWS2H + (long)kNTOT * kF2 / 2;

__device__ __align__(16) float g_scratch[SCRATCH_FLOATS];

// ---------------------------------------------------------------------------
// mma / ldmatrix helpers
// ---------------------------------------------------------------------------
__device__ __forceinline__ void mma_f16(float* d, const uint32_t* a,
                                        uint32_t b0, uint32_t b1) {
    asm volatile(
        "mma.sync.aligned.m16n8k16.row.col.f32.f16.f16.f32 "
        "{%0,%1,%2,%3},{%4,%5,%6,%7},{%8,%9},{%0,%1,%2,%3};"
        : "+f"(d[0]), "+f"(d[1]), "+f"(d[2]), "+f"(d[3])
        : "r"(a[0]), "r"(a[1]), "r"(a[2]), "r"(a[3]), "r"(b0), "r"(b1));
}
__device__ __forceinline__ void ldsm4(uint32_t* r, uint32_t addr) {
    asm volatile("ldmatrix.sync.aligned.m8n8.x4.shared.b16 {%0,%1,%2,%3}, [%4];"
                 : "=r"(r[0]), "=r"(r[1]), "=r"(r[2]), "=r"(r[3]) : "r"(addr));
}
__device__ __forceinline__ void ldsm4t(uint32_t* r, uint32_t addr) {
    asm volatile("ldmatrix.sync.aligned.m8n8.x4.trans.shared.b16 {%0,%1,%2,%3}, [%4];"
                 : "=r"(r[0]), "=r"(r[1]), "=r"(r[2]), "=r"(r[3]) : "r"(addr));
}
__device__ __forceinline__ uint32_t smem_u32(const void* p) {
    return (uint32_t)__cvta_generic_to_shared(p);
}
__device__ __forceinline__ uint32_t h2u(__half2 h) {
    return *reinterpret_cast<uint32_t*>(&h);
}

// ---------------------------------------------------------------------------
// Small kernels
// ---------------------------------------------------------------------------
__global__ void k_zeroS(int* degS, float* h1) {
    int i = blockIdx.x * 256 + threadIdx.x;
    if (i < kNTOT) degS[i] = 0;
    if (i < kBZ * 256) h1[i] = 0.f;
}

__global__ void k_lslr(const float* __restrict__ t, const float* __restrict__ fcw,
                       const float* __restrict__ fcb,
                       float* __restrict__ Eg, float* __restrict__ Fg) {
    int warp = (blockIdx.x * blockDim.x + threadIdx.x) >> 5;
    int lane = threadIdx.x & 31;
    if (warp >= kNTOT) return;
    const float* tn = t + (long)warp * kTC;
    const float* w0 = fcw;
    const float* w1 = fcw + 512;
    float s0 = 0.f, s1 = 0.f, r0 = 0.f, r1 = 0.f;
#pragma unroll
    for (int q = 0; q < 8; q++) {
        int d = lane + 32 * q;
        float u = fmaxf(tn[d], 0.f);
        s0 += u * w0[d];       s1 += u * w1[d];
        r0 += u * w0[256 + d]; r1 += u * w1[256 + d];
    }
#pragma unroll
    for (int off = 16; off; off >>= 1) {
        s0 += __shfl_down_sync(0xffffffffu, s0, off);
        s1 += __shfl_down_sync(0xffffffffu, s1, off);
        r0 += __shfl_down_sync(0xffffffffu, r0, off);
        r1 += __shfl_down_sync(0xffffffffu, r1, off);
    }
    if (lane == 0) {
        Eg[warp] = expf(r1 - r0 + fcb[1] - fcb[0]);
        Fg[warp] = expf(s1 - s0);
    }
}

__global__ void k_buildA(const float* __restrict__ gu,
                         const float* __restrict__ Eg, const float* __restrict__ Fg,
                         unsigned char* __restrict__ A8) {
    int idx = blockIdx.x * 256 + threadIdx.x;
    int j0 = (idx & 127) << 2;
    int i  = (idx >> 7) & 511;
    int b  = idx >> 16;
    float Ei = Eg[b * kN + i];
    float4 Fv = *reinterpret_cast<const float4*>(Fg + b * kN + j0);
    const float4* g4 = reinterpret_cast<const float4*>(
        gu + ((long)(b * kN + i) * kN + j0) * 2);
    float4 u01 = g4[0];
    float4 u23 = g4[1];
    auto bit = [&](float ux, float uy, float Fj) -> unsigned char {
        ux = fminf(fmaxf(ux, 1e-9f), 1.0f - 1e-9f);
        uy = fminf(fmaxf(uy, 1e-9f), 1.0f - 1e-9f);
        float l0 = -__logf(ux);
        float l1 = -__logf(uy);
        return (l1 >= l0 * Ei * Fj) ? 1 : 0;
    };
    uchar4 r;
    r.x = bit(u01.x, u01.y, Fv.x);
    r.y = bit(u01.z, u01.w, Fv.y);
    r.z = bit(u23.x, u23.y, Fv.z);
    r.w = bit(u23.z, u23.w, Fv.w);
    *reinterpret_cast<uchar4*>(A8 + (long)(b * kN + i) * kN + j0) = r;
}

__global__ void k_colsum_part(const unsigned char* __restrict__ A8,
                              float* __restrict__ part) {
    int b = blockIdx.x;
    int j = threadIdx.x;
    int r0 = blockIdx.y * 64;
    const unsigned char* Ab = A8 + (long)b * kN * kN;
    int s = 0;
#pragma unroll 8
    for (int r = r0; r < r0 + 64; r++) s += Ab[(long)r * kN + j];
    part[((long)b * 8 + blockIdx.y) * kN + j] = (float)s;
}

__global__ void k_disD(const float* __restrict__ part, float* __restrict__ disD) {
    int i = blockIdx.x * 256 + threadIdx.x;
    if (i >= kNTOT) return;
    int b = i >> 9, j = i & 511;
    float s = 1.f;
#pragma unroll
    for (int c = 0; c < 8; c++) s += part[((long)b * 8 + c) * kN + j];
    disD[i] = rsqrtf(s);
}

__global__ void k_degS(const int* __restrict__ colp, int* degS) {
    int e = blockIdx.x * 256 + threadIdx.x;
    if (e < kE) atomicAdd(&degS[colp[e]], 1);
}

__global__ void k_disS(const int* __restrict__ degS, float* __restrict__ disS) {
    int i = blockIdx.x * 256 + threadIdx.x;
    if (i < kNTOT) disS[i] = rsqrtf((float)degS[i] + 1.f);
}

__global__ void k_scan(const int* __restrict__ degS, int* __restrict__ ns,
                       int* __restrict__ cur) {
    __shared__ int sm[1024];
    int tid = threadIdx.x;
    int base = tid * 16;
    int local[16];
    int sum = 0;
#pragma unroll
    for (int v = 0; v < 16; v++) { local[v] = degS[base + v]; sum += local[v]; }
    sm[tid] = sum;
    __syncthreads();
    for (int off = 1; off < 1024; off <<= 1) {
        int v = (tid >= off) ? sm[tid - off] : 0;
        __syncthreads();
        sm[tid] += v;
        __syncthreads();
    }
    int run = sm[tid] - sum;
#pragma unroll
    for (int v = 0; v < 16; v++) {
        ns[base + v] = run;
        cur[base + v] = run;
        run += local[v];
    }
    if (tid == 1023) ns[kNTOT] = run;
}

__global__ void k_fill(const int* __restrict__ rowp, const int* __restrict__ colp,
                       int* cur, int* __restrict__ esrc) {
    int e = blockIdx.x * 256 + threadIdx.x;
    if (e < kE) {
        int c = colp[e];
        int p = atomicAdd(&cur[c], 1);
        esrc[p] = rowp[e];
    }
}

// ---------------------------------------------------------------------------
// fp16 CSR gather: WPN warps per node, VH half2 per lane.
// ---------------------------------------------------------------------------
template <int WPN, int VH>
__global__ __launch_bounds__(256) void k_gather_h(
        const int* __restrict__ ns, const int* __restrict__ esrc,
        const __half2* __restrict__ xwh, const float* __restrict__ disS,
        const float* __restrict__ bias, float* __restrict__ out,
        int outStride, int outOffset) {
    constexpr int F2 = WPN * VH * 32;
    int gw = (blockIdx.x * 256 + threadIdx.x) >> 5;
    int lane = threadIdx.x & 31;
    int node = gw / WPN;
    int part = gw % WPN;
    if (node >= kNTOT) return;
    int off2 = (part * 32 + lane) * VH;
    float dc = disS[node];
    float2 acc[VH];

    auto loadrow = [&](long r, uint32_t* rw) {
        const char* p = reinterpret_cast<const char*>(xwh + r * F2 + off2);
        if (VH == 4) {
            uint4 u = *reinterpret_cast<const uint4*>(p);
            rw[0] = u.x; rw[1] = u.y; rw[2] = u.z; rw[3] = u.w;
        } else {
            uint2 u = *reinterpret_cast<const uint2*>(p);
            rw[0] = u.x; rw[1] = u.y;
        }
    };

    {
        uint32_t rw[VH];
        loadrow(node, rw);
        float d2 = dc * dc;
#pragma unroll
        for (int v = 0; v < VH; v++) {
            float2 xv = __half22float2(*reinterpret_cast<__half2*>(&rw[v]));
            float2 bb = *reinterpret_cast<const float2*>(bias + (off2 + v) * 2);
            acc[v] = make_float2(xv.x * d2 + bb.x, xv.y * d2 + bb.y);
        }
    }
    int s = ns[node], e = ns[node + 1];
    int i = s;
    for (; i + 8 <= e; i += 8) {
        int r[8];
        float sc[8];
        uint32_t rw[8][VH];
#pragma unroll
        for (int q = 0; q < 8; q++) r[q] = esrc[i + q];
#pragma unroll
        for (int q = 0; q < 8; q++) sc[q] = disS[r[q]] * dc;
#pragma unroll
        for (int q = 0; q < 8; q++) loadrow(r[q], rw[q]);
#pragma unroll
        for (int q = 0; q < 8; q++)
#pragma unroll
            for (int v = 0; v < VH; v++) {
                float2 xv = __half22float2(*reinterpret_cast<__half2*>(&rw[q][v]));
                acc[v].x += xv.x * sc[q];
                acc[v].y += xv.y * sc[q];
            }
    }
    for (; i < e; i++) {
        int r = esrc[i];
        float sr = disS[r] * dc;
        uint32_t rw[VH];
        loadrow(r, rw);
#pragma unroll
        for (int v = 0; v < VH; v++) {
            float2 xv = __half22float2(*reinterpret_cast<__half2*>(&rw[v]));
            acc[v].x += xv.x * sr;
            acc[v].y += xv.y * sr;
        }
    }
    float* op = out + (long)node * outStride + outOffset + off2 * 2;
#pragma unroll
    for (int v = 0; v < VH; v++)
        *reinterpret_cast<float2*>(op + v * 2) = acc[v];
}

// ---------------------------------------------------------------------------
// fp16 HMMA NT GEMM (m16n8k16, fp32 accum): C = A[MxK] @ B[NfxK]^T
// fp32 sources converted to half on tile store. fp32/fp16 outputs optional.
// SMEM [128][24] halves: row stride 48B -> 8-row ldmatrix phases hit all banks.
// ---------------------------------------------------------------------------
template <bool RELU_A>
__global__ __launch_bounds__(256) void k_gemm_h(
        const float* __restrict__ A,
        const float* __restrict__ B,
        float* __restrict__ C,
        int Nf, int K, __half* __restrict__ Ch) {
    __shared__ __half As[2][128][24];
    __shared__ __half Bs[2][128][24];
    int m0 = blockIdx.y * 128, n0 = blockIdx.x * 128;
    int t = threadIdx.x;
    int wid = t >> 5, lane = t & 31;
    int mw = (wid >> 1) * 32, nw = (wid & 1) * 64;
    int g = lane >> 2, tg = lane & 3;
    int lrow = (lane & 7) + ((lane >> 3) & 1) * 8;  // ldmatrix row within 16
    int kc   = (lane >> 4) * 8;                     // ldmatrix k-half
    int lr = t >> 1, lc8 = (t & 1) * 8;             // loader: row, half-offset

    uint32_t sA[2] = { smem_u32(&As[0][0][0]), smem_u32(&As[1][0][0]) };
    uint32_t sB[2] = { smem_u32(&Bs[0][0][0]), smem_u32(&Bs[1][0][0]) };

    float acc[2][8][4];
#pragma unroll
    for (int i = 0; i < 2; i++)
#pragma unroll
        for (int j = 0; j < 8; j++)
#pragma unroll
            for (int c = 0; c < 4; c++) acc[i][j][c] = 0.f;

    const float* aP = A + (long)(m0 + lr) * K + lc8;
    const float* bP = B + (long)(n0 + lr) * K + lc8;

    auto cvt8 = [](float4 f0, float4 f1, bool relu) -> uint4 {
        if (relu) {
            f0.x = fmaxf(f0.x, 0.f); f0.y = fmaxf(f0.y, 0.f);
            f0.z = fmaxf(f0.z, 0.f); f0.w = fmaxf(f0.w, 0.f);
            f1.x = fmaxf(f1.x, 0.f); f1.y = fmaxf(f1.y, 0.f);
            f1.z = fmaxf(f1.z, 0.f); f1.w = fmaxf(f1.w, 0.f);
        }
        uint4 u;
        u.x = h2u(__floats2half2_rn(f0.x, f0.y));
        u.y = h2u(__floats2half2_rn(f0.z, f0.w));
        u.z = h2u(__floats2half2_rn(f1.x, f1.y));
        u.w = h2u(__floats2half2_rn(f1.z, f1.w));
        return u;
    };

    {
        uint4 ua = cvt8(*reinterpret_cast<const float4*>(aP),
                        *reinterpret_cast<const float4*>(aP + 4), RELU_A);
        uint4 ub = cvt8(*reinterpret_cast<const float4*>(bP),
                        *reinterpret_cast<const float4*>(bP + 4), false);
        *reinterpret_cast<uint4*>(&As[0][lr][lc8]) = ua;
        *reinterpret_cast<uint4*>(&Bs[0][lr][lc8]) = ub;
    }
    __syncthreads();

    int buf = 0;
    for (int k0 = 0; k0 < K; k0 += 16) {
        bool more = (k0 + 16) < K;
        float4 na0, na1, nb0, nb1;
        if (more) {
            na0 = *reinterpret_cast<const float4*>(aP + k0 + 16);
            na1 = *reinterpret_cast<const float4*>(aP + k0 + 20);
            nb0 = *reinterpret_cast<const float4*>(bP + k0 + 16);
            nb1 = *reinterpret_cast<const float4*>(bP + k0 + 20);
        }
        {
            uint32_t af0[4], af1[4];
            ldsm4(af0, sA[buf] + ((mw + lrow) * 24 + kc) * 2);
            ldsm4(af1, sA[buf] + ((mw + 16 + lrow) * 24 + kc) * 2);
#pragma unroll
            for (int p = 0; p < 4; p++) {
                uint32_t bf[4];
                ldsm4(bf, sB[buf] + ((nw + p * 16 + lrow) * 24 + kc) * 2);
                mma_f16(acc[0][2 * p],     af0, bf[0], bf[2]);
                mma_f16(acc[0][2 * p + 1], af0, bf[1], bf[3]);
                mma_f16(acc[1][2 * p],     af1, bf[0], bf[2]);
                mma_f16(acc[1][2 * p + 1], af1, bf[1], bf[3]);
            }
        }
        if (more) {
            int nb = buf ^ 1;
            *reinterpret_cast<uint4*>(&As[nb][lr][lc8]) = cvt8(na0, na1, RELU_A);
            *reinterpret_cast<uint4*>(&Bs[nb][lr][lc8]) = cvt8(nb0, nb1, false);
            __syncthreads();
            buf = nb;
        }
    }

#pragma unroll
    for (int mt = 0; mt < 2; mt++) {
        int row = m0 + mw + mt * 16 + g;
#pragma unroll
        for (int j = 0; j < 8; j++) {
            int col = n0 + nw + j * 8 + 2 * tg;
            float2 v0 = make_float2(acc[mt][j][0], acc[mt][j][1]);
            float2 v1 = make_float2(acc[mt][j][2], acc[mt][j][3]);
            if (C) {
                *reinterpret_cast<float2*>(C + (long)row * Nf + col) = v0;
                *reinterpret_cast<float2*>(C + (long)(row + 8) * Nf + col) = v1;
            }
            if (Ch) {
                *reinterpret_cast<__half2*>(Ch + (long)row * Nf + col) =
                    __floats2half2_rn(v0.x, v0.y);
                *reinterpret_cast<__half2*>(Ch + (long)(row + 8) * Nf + col) =
                    __floats2half2_rn(v1.x, v1.y);
            }
        }
    }
}

// ---------------------------------------------------------------------------
// fp16 HMMA dense GCN propagation (m16n8k16, fp32 accum) — unchanged from R13
// ---------------------------------------------------------------------------
template <bool RELU, bool XHALF>
__global__ __launch_bounds__(256) void k_prop_h(
        const unsigned char* __restrict__ Adj8, const void* __restrict__ XWv,
        const float* __restrict__ dis, const float* __restrict__ bias,
        float* __restrict__ out, int F, int outStride, int outOffset) {
    __shared__ __half As[2][16][136];
    __shared__ __half Bs[2][16][136];
    int b = blockIdx.z;
    const unsigned char* Ab = Adj8 + (long)b * kN * kN;
    const float* Xf = XHALF ? nullptr : (const float*)XWv + (long)b * kN * F;
    const __half* Xh = XHALF ? (const __half*)XWv + (long)b * kN * F : nullptr;
    const float* db = dis + b * kN;
    float* Ob = out + (long)b * kN * outStride + outOffset;
    int i0 = blockIdx.y * 128, f0 = blockIdx.x * 128;
    int t = threadIdx.x;
    int wid = t >> 5, lane = t & 31;
    int mw = (wid >> 1) * 32, nw = (wid & 1) * 64;
    int g = lane >> 2, tg = lane & 3;
    int jj = t >> 4;
    int ii = (t & 15) << 3;

    int l8 = lane & 7;
    int gA_k = (lane >> 4) * 8 + l8;
    int gA_m = ((lane >> 3) & 1) * 8;
    int gB_k = ((lane >> 3) & 1) * 8 + l8;
    int gB_n = (lane >> 4) * 8;

    uint32_t sAb[2] = { smem_u32(&As[0][0][0]), smem_u32(&As[1][0][0]) };
    uint32_t sBb[2] = { smem_u32(&Bs[0][0][0]), smem_u32(&Bs[1][0][0]) };

    float acc[2][8][4];
#pragma unroll
    for (int i = 0; i < 2; i++)
#pragma unroll
        for (int j = 0; j < 8; j++)
#pragma unroll
            for (int c = 0; c < 4; c++) acc[i][j][c] = 0.f;

    auto ldX8 = [&](int row, float* xv) {
        if (XHALF) {
            uint4 raw = *reinterpret_cast<const uint4*>(Xh + (long)row * F + f0 + ii);
            const __half2* hp = reinterpret_cast<const __half2*>(&raw);
#pragma unroll
            for (int v = 0; v < 4; v++) {
                float2 f = __half22float2(hp[v]);
                xv[2 * v] = f.x; xv[2 * v + 1] = f.y;
            }
        } else {
            *reinterpret_cast<float4*>(xv) =
                *reinterpret_cast<const float4*>(Xf + (long)row * F + f0 + ii);
            *reinterpret_cast<float4*>(xv + 4) =
                *reinterpret_cast<const float4*>(Xf + (long)row * F + f0 + ii + 4);
        }
    };

    auto hb = [](uint32_t byte) -> uint32_t { return byte ? 0x3C00u : 0u; };

    auto stTile = [&](int bufI, uint2 rawA, const float* xv, float dj) {
        uint4 ua;
        ua.x = hb(rawA.x & 0xffu)         | (hb((rawA.x >> 8) & 0xffu) << 16);
        ua.y = hb((rawA.x >> 16) & 0xffu) | (hb(rawA.x >> 24) << 16);
        ua.z = hb(rawA.y & 0xffu)         | (hb((rawA.y >> 8) & 0xffu) << 16);
        ua.w = hb((rawA.y >> 16) & 0xffu) | (hb(rawA.y >> 24) << 16);
        uint4 ub;
        ub.x = h2u(__floats2half2_rn(xv[0] * dj, xv[1] * dj));
        ub.y = h2u(__floats2half2_rn(xv[2] * dj, xv[3] * dj));
        ub.z = h2u(__floats2half2_rn(xv[4] * dj, xv[5] * dj));
        ub.w = h2u(__floats2half2_rn(xv[6] * dj, xv[7] * dj));
        *reinterpret_cast<uint4*>(&As[bufI][jj][ii]) = ua;
        *reinterpret_cast<uint4*>(&Bs[bufI][jj][ii]) = ub;
    };

    {
        uint2 rawA = *reinterpret_cast<const uint2*>(Ab + (long)jj * kN + i0 + ii);
        float xv[8];
        ldX8(jj, xv);
        stTile(0, rawA, xv, db[jj]);
    }
    __syncthreads();

    int buf = 0;
    for (int j0 = 0; j0 < kN; j0 += 16) {
        bool more = (j0 + 16) < kN;
        uint2 nraw;
        float nxv[8];
        float djn = 0.f;
        if (more) {
            nraw = *reinterpret_cast<const uint2*>(
                Ab + (long)(j0 + 16 + jj) * kN + i0 + ii);
            ldX8(j0 + 16 + jj, nxv);
            djn = db[j0 + 16 + jj];
        }
        {
            uint32_t a0[4], a1[4];
            ldsm4t(a0, sAb[buf] + (gA_k * 136 + mw + gA_m) * 2);
            ldsm4t(a1, sAb[buf] + (gA_k * 136 + mw + 16 + gA_m) * 2);
#pragma unroll
            for (int p = 0; p < 4; p++) {
                uint32_t bf[4];
                ldsm4t(bf, sBb[buf] + (gB_k * 136 + nw + p * 16 + gB_n) * 2);
                mma_f16(acc[0][2 * p],     a0, bf[0], bf[1]);
                mma_f16(acc[0][2 * p + 1], a0, bf[2], bf[3]);
                mma_f16(acc[1][2 * p],     a1, bf[0], bf[1]);
                mma_f16(acc[1][2 * p + 1], a1, bf[2], bf[3]);
            }
        }
        if (more) {
            int nb = buf ^ 1;
            stTile(nb, nraw, nxv, djn);
            __syncthreads();
            buf = nb;
        }
    }

#pragma unroll
    for (int mt = 0; mt < 2; mt++) {
        int rowA = i0 + mw + mt * 16 + g;
        float diA = db[rowA], diB = db[rowA + 8];
#pragma unroll
        for (int j = 0; j < 8; j++) {
            int col = f0 + nw + j * 8 + 2 * tg;
            float2 bb = *reinterpret_cast<const float2*>(bias + col);
            float2 xA, xB;
            if (XHALF) {
                xA = __half22float2(*reinterpret_cast<const __half2*>(
                    Xh + (long)rowA * F + col));
                xB = __half22float2(*reinterpret_cast<const __half2*>(
                    Xh + (long)(rowA + 8) * F + col));
            } else {
                xA = *reinterpret_cast<const float2*>(Xf + (long)rowA * F + col);
                xB = *reinterpret_cast<const float2*>(Xf + (long)(rowA + 8) * F + col);
            }
            float v0 = diA * (acc[mt][j][0] + diA * xA.x) + bb.x;
            float v1 = diA * (acc[mt][j][1] + diA * xA.y) + bb.y;
            float v2 = diB * (acc[mt][j][2] + diB * xB.x) + bb.x;
            float v3 = diB * (acc[mt][j][3] + diB * xB.y) + bb.y;
            if (RELU) {
                v0 = fmaxf(v0, 0.f); v1 = fmaxf(v1, 0.f);
                v2 = fmaxf(v2, 0.f); v3 = fmaxf(v3, 0.f);
            }
            *reinterpret_cast<float2*>(Ob + (long)rowA * outStride + col) =
                make_float2(v0, v1);
            *reinterpret_cast<float2*>(Ob + (long)(rowA + 8) * outStride + col) =
                make_float2(v2, v3);
        }
    }
}

// ---------------------------------------------------------------------------
// fcn1 half (strided k-half), double-buffered
// ---------------------------------------------------------------------------
__global__ void k_fcn1_half(const float* __restrict__ emb, const float* __restrict__ W,
                            float* __restrict__ h1, int colOff) {
    constexpr int KH = kKTOT / 2;
    constexpr int KC = KH / 64;     // 1024
    __shared__ float As[16][32];
    __shared__ float Bs[16][64];
    int n0 = blockIdx.x * 64;
    int kbase = blockIdx.y * KC;
    int t = threadIdx.x;
    int m = t & 31;
    int nb = (t >> 5) << 3;
    int row = t >> 2, c4 = (t & 3) << 2;
    float acc[8];
#pragma unroll
    for (int j = 0; j < 8; j++) acc[j] = 0.f;

    auto kmap = [&](int k) -> long {
        return ((long)(k >> 7) << 8) + colOff + (k & 127);
    };

    float4 aPre, bPre;
    if (t < 128)
        aPre = *reinterpret_cast<const float4*>(emb + (long)row * kKTOT + kmap(kbase + c4));
    bPre = *reinterpret_cast<const float4*>(W + (long)(n0 + row) * kKTOT + kmap(kbase + c4));

    for (int k0 = kbase; k0 < kbase + KC; k0 += 16) {
        if (t < 128) {
            As[c4 + 0][row] = aPre.x; As[c4 + 1][row] = aPre.y;
            As[c4 + 2][row] = aPre.z; As[c4 + 3][row] = aPre.w;
        }
        Bs[c4 + 0][row] = bPre.x; Bs[c4 + 1][row] = bPre.y;
        Bs[c4 + 2][row] = bPre.z; Bs[c4 + 3][row] = bPre.w;
        __syncthreads();
        bool more = (k0 + 16) < kbase + KC;
        if (more) {
            if (t < 128)
                aPre = *reinterpret_cast<const float4*>(
                    emb + (long)row * kKTOT + kmap(k0 + 16 + c4));
            bPre = *reinterpret_cast<const float4*>(
                W + (long)(n0 + row) * kKTOT + kmap(k0 + 16 + c4));
        }
#pragma unroll
        for (int k = 0; k < 16; k++) {
            float a = As[k][m];
#pragma unroll
            for (int j = 0; j < 8; j++) acc[j] += a * Bs[k][nb + j];
        }
        __syncthreads();
    }
#pragma unroll
    for (int j = 0; j < 8; j++)
        atomicAdd(&h1[m * 256 + n0 + nb + j], acc[j]);
}

__global__ void k_fcn23(const float* __restrict__ h1g,
                        const float* __restrict__ b1, const float* __restrict__ w2,
                        const float* __restrict__ b2, const float* __restrict__ w3,
                        const float* __restrict__ b3, float* __restrict__ out) {
    __shared__ float h1s[32][256];
    __shared__ float h2s[32][32];
    int t = threadIdx.x;
    for (int idx = t; idx < 32 * 256; idx += 1024) {
        float v = h1g[idx] + b1[idx & 255];
        h1s[idx >> 8][idx & 255] = (v >= 0.f) ? v : 0.2f * v;
    }
    __syncthreads();
    {
        int b = t >> 5, o = t & 31;
        float s = 0.f;
#pragma unroll 8
        for (int k = 0; k < 256; k++) s += h1s[b][k] * w2[o * 256 + k];
        s += b2[o];
        h2s[b][o] = (s >= 0.f) ? s : 0.2f * s;
    }
    __syncthreads();
    if (t < 64) {
        int b = t >> 1, o = t & 1;
        float s = 0.f;
#pragma unroll
        for (int k = 0; k < 32; k++) s += h2s[b][k] * w3[o * 32 + k];
        out[b * 2 + o] = s + b3[o];
    }
}

// ---------------------------------------------------------------------------
// Launch
// ---------------------------------------------------------------------------
extern "C" void kernel_launch(void* const* d_in, const int* in_sizes, int n_in,
                              void* d_out, int out_size) {
    const float* x    = (const float*)d_in[0];
    const float* t    = (const float*)d_in[1];
    const float* gu   = (const float*)d_in[2];
    const int*   ei   = (const int*)d_in[3];
    const float* w1   = (const float*)d_in[4];
    const float* b1   = (const float*)d_in[5];
    const float* w2   = (const float*)d_in[6];
    const float* b2   = (const float*)d_in[7];
    const float* fcw  = (const float*)d_in[8];
    const float* fcb  = (const float*)d_in[9];
    const float* f1w  = (const float*)d_in[10];
    const float* f1b  = (const float*)d_in[11];
    const float* f2w  = (const float*)d_in[12];
    const float* f2b  = (const float*)d_in[13];
    const float* f3w  = (const float*)d_in[14];
    const float* f3b  = (const float*)d_in[15];
    float* out = (float*)d_out;

    const int* rowp = ei;
    const int* colp = ei + kE;

    float* base = nullptr;
    cudaGetSymbolAddress((void**)&base, g_scratch);
    float* p_E     = base + OFF_EG;
    float* p_F     = base + OFF_FG;
    unsigned char* p_A8 = (unsigned char*)(base + OFF_A8);
    float* p_disD  = base + OFF_DISD;
    float* p_part  = base + OFF_PART;
    float* p_h     = base + OFF_H;
    float* p_sc1   = base + OFF_SC1;
    float* p_xw2   = base + OFF_XW2;
    float* p_emb   = base + OFF_EMB;
    float* p_disS  = base + OFF_DISS;
    int*   p_degS  = (int*)(base + OFF_DEGS);
    float* p_h1    = base + OFF_H1;
    int*   p_ns    = (int*)(base + OFF_NS);
    int*   p_cur   = (int*)(base + OFF_CUR);
    int*   p_esrc  = (int*)(base + OFF_ESRC);
    __half* p_xw1h  = (__half*)(base + OFF_XW1H);
    __half* p_xws2h = (__half*)(base + OFF_XWS2H);

    static cudaStream_t sG = nullptr, sC = nullptr;
    static cudaEvent_t evStart, evZ, evG1, evCSR, evF1s;
    if (!sG) {
        cudaStreamCreateWithFlags(&sG, cudaStreamNonBlocking);
        cudaStreamCreateWithFlags(&sC, cudaStreamNonBlocking);
        cudaEventCreateWithFlags(&evStart, cudaEventDisableTiming);
        cudaEventCreateWithFlags(&evZ, cudaEventDisableTiming);
        cudaEventCreateWithFlags(&evG1, cudaEventDisableTiming);
        cudaEventCreateWithFlags(&evCSR, cudaEventDisableTiming);
        cudaEventCreateWithFlags(&evF1s, cudaEventDisableTiming);
    }

    cudaEventRecord(evStart, 0);
    cudaStreamWaitEvent(sG, evStart, 0);
    cudaStreamWaitEvent(sC, evStart, 0);

    // main: zero + dense prep
    k_zeroS<<<64, 256>>>(p_degS, p_h1);
    cudaEventRecord(evZ, 0);
    k_lslr<<<kNTOT / 8, 256>>>(t, fcw, fcb, p_E, p_F);
    k_buildA<<<kBZ * kN * kN / 1024, 256>>>(gu, p_E, p_F, p_A8);

    // sG: gemm1 — fp16 output only (captured slot)
    k_gemm_h<false><<<dim3(kF1 / 128, kNTOT / 128, 1), 256, 0, sG>>>(
        x, w1, nullptr, kF1, kN, p_xw1h);
    cudaEventRecord(evG1, sG);

    // main: dense degrees (atomic-free)
    k_colsum_part<<<dim3(kBZ, 8), kN>>>(p_A8, p_part);
    k_disD<<<kNTOT / 256, 256>>>(p_part, p_disD);

    // sC: CSR chain
    cudaStreamWaitEvent(sC, evZ, 0);
    k_degS<<<kE / 256, 256, 0, sC>>>(colp, p_degS);
    k_disS<<<kNTOT / 256, 256, 0, sC>>>(p_degS, p_disS);
    k_scan<<<1, 1024, 0, sC>>>(p_degS, p_ns, p_cur);
    k_fill<<<kE / 256, 256, 0, sC>>>(rowp, colp, p_cur, p_esrc);
    cudaEventRecord(evCSR, sC);

    // ===== dense pipeline (main) =====
    cudaStreamWaitEvent(0, evG1, 0);
    k_prop_h<true, true><<<dim3(kF1 / 128, kN / 128, kBZ), 256>>>(
        p_A8, p_xw1h, p_disD, b1, p_h, kF1, kF1, 0);
    k_gemm_h<true><<<dim3(kF2 / 128, kNTOT / 128, 1), 256>>>(
        p_h, w2, p_xw2, kF2, kF1, nullptr);
    k_prop_h<false, false><<<dim3(kF2 / 128, kN / 128, kBZ), 256>>>(
        p_A8, p_xw2, p_disD, b2, p_emb, kF2, 256, 0);
    k_fcn1_half<<<dim3(4, 64), 256>>>(p_emb, f1w, p_h1, 0);

    // ===== sparse pipeline (sG) =====
    cudaStreamWaitEvent(sG, evCSR, 0);
    k_gather_h<2, 2><<<kNTOT * 2 / 8, 256, 0, sG>>>(p_ns, p_esrc,
        (const __half2*)p_xw1h, p_disS, b1, p_sc1, kF1, 0);
    k_gemm_h<true><<<dim3(kF2 / 128, kNTOT / 128, 1), 256, 0, sG>>>(
        p_sc1, w2, nullptr, kF2, kF1, p_xws2h);
    k_gather_h<1, 2><<<kNTOT / 8, 256, 0, sG>>>(p_ns, p_esrc,
        (const __half2*)p_xws2h, p_disS, b2, p_emb, 256, 128);
    k_fcn1_half<<<dim3(4, 64), 256, 0, sG>>>(p_emb, f1w, p_h1, 128);
    cudaEventRecord(evF1s, sG);

    // join + head
    cudaStreamWaitEvent(0, evF1s, 0);
    k_fcn23<<<1, 1024>>>(p_h1, f1b, f2w, f2b, f3w, f3b, out);
}

// round 15
// speedup vs baseline: 1.1016x; 1.1016x over previous
#include <cuda_runtime.h>
#include <cuda_fp16.h>
#include <cstdint>

// ---------------------------------------------------------------------------
// Problem constants
// ---------------------------------------------------------------------------
constexpr int kN    = 512;
constexpr int kBZ   = 32;
constexpr int kTC   = 256;
constexpr int kF1   = 256;
constexpr int kF2   = 128;
constexpr int kE    = 524288;
constexpr int kNTOT = kBZ * kN;          // 16384
constexpr int kKTOT = kF2 * 2 * kN;      // 131072

// ---------------------------------------------------------------------------
// Scratch (offsets in floats)
// ---------------------------------------------------------------------------
constexpr long OFF_EG   = 0;
constexpr long OFF_FG   = OFF_EG   + (long)kNTOT;
constexpr long OFF_A8   = OFF_FG   + (long)kNTOT;                // u8 view
constexpr long OFF_DISD = OFF_A8   + (long)kBZ * kN * kN / 4;
constexpr long OFF_PART = OFF_DISD + (long)kNTOT;                // 32*8*512
constexpr long OFF_H    = OFF_PART + (long)kBZ * 8 * kN;
constexpr long OFF_SC1  = OFF_H    + (long)kNTOT * kF1;
constexpr long OFF_XW2H = OFF_SC1  + (long)kNTOT * kF1;          // half, NTOT*F2
constexpr long OFF_EMB  = OFF_XW2H + (long)kNTOT * kF2 / 2;
constexpr long OFF_DISS = OFF_EMB  + (long)kNTOT * 256;
constexpr long OFF_DEGS = OFF_DISS + (long)kNTOT;                // int
constexpr long OFF_H1   = OFF_DEGS + (long)kNTOT;
constexpr long OFF_NS   = OFF_H1   + (long)kBZ * 256;            // int, kNTOT+1
constexpr long OFF_CUR  = OFF_NS   + (long)kNTOT + 4;            // int
constexpr long OFF_ESRC = OFF_CUR  + (long)kNTOT;                // int, kE
constexpr long OFF_XW1H = OFF_ESRC + (long)kE;                   // half, NTOT*F1
constexpr long OFF_XWS2H= OFF_XW1H + (long)kNTOT * kF1 / 2;      // half, NTOT*F2
constexpr long SCRATCH_FLOATS = OFF_XWS2H + (long)kNTOT * kF2 / 2;

__device__ __align__(16) float g_scratch[SCRATCH_FLOATS];

// ---------------------------------------------------------------------------
// mma / ldmatrix helpers
// ---------------------------------------------------------------------------
__device__ __forceinline__ uint32_t f2tf(float x) {
    uint32_t r;
    asm("cvt.rna.tf32.f32 %0, %1;" : "=r"(r) : "f"(x));
    return r;
}
__device__ __forceinline__ void mma_tf32(float* d, const uint32_t* a,
                                         uint32_t b0, uint32_t b1) {
    asm volatile(
        "mma.sync.aligned.m16n8k8.row.col.f32.tf32.tf32.f32 "
        "{%0,%1,%2,%3},{%4,%5,%6,%7},{%8,%9},{%0,%1,%2,%3};"
        : "+f"(d[0]), "+f"(d[1]), "+f"(d[2]), "+f"(d[3])
        : "r"(a[0]), "r"(a[1]), "r"(a[2]), "r"(a[3]), "r"(b0), "r"(b1));
}
__device__ __forceinline__ void mma_f16(float* d, const uint32_t* a,
                                        uint32_t b0, uint32_t b1) {
    asm volatile(
        "mma.sync.aligned.m16n8k16.row.col.f32.f16.f16.f32 "
        "{%0,%1,%2,%3},{%4,%5,%6,%7},{%8,%9},{%0,%1,%2,%3};"
        : "+f"(d[0]), "+f"(d[1]), "+f"(d[2]), "+f"(d[3])
        : "r"(a[0]), "r"(a[1]), "r"(a[2]), "r"(a[3]), "r"(b0), "r"(b1));
}
__device__ __forceinline__ void ldsm4(uint32_t* r, uint32_t addr) {
    asm volatile("ldmatrix.sync.aligned.m8n8.x4.shared.b16 {%0,%1,%2,%3}, [%4];"
                 : "=r"(r[0]), "=r"(r[1]), "=r"(r[2]), "=r"(r[3]) : "r"(addr));
}
__device__ __forceinline__ void ldsm4t(uint32_t* r, uint32_t addr) {
    asm volatile("ldmatrix.sync.aligned.m8n8.x4.trans.shared.b16 {%0,%1,%2,%3}, [%4];"
                 : "=r"(r[0]), "=r"(r[1]), "=r"(r[2]), "=r"(r[3]) : "r"(addr));
}
__device__ __forceinline__ uint32_t smem_u32(const void* p) {
    return (uint32_t)__cvta_generic_to_shared(p);
}
__device__ __forceinline__ uint32_t h2u(__half2 h) {
    return *reinterpret_cast<uint32_t*>(&h);
}

// ---------------------------------------------------------------------------
// Small kernels
// ---------------------------------------------------------------------------
__global__ void k_zeroS(int* degS, float* h1) {
    int i = blockIdx.x * 256 + threadIdx.x;
    if (i < kNTOT) degS[i] = 0;
    if (i < kBZ * 256) h1[i] = 0.f;
}

__global__ void k_lslr(const float* __restrict__ t, const float* __restrict__ fcw,
                       const float* __restrict__ fcb,
                       float* __restrict__ Eg, float* __restrict__ Fg) {
    int warp = (blockIdx.x * blockDim.x + threadIdx.x) >> 5;
    int lane = threadIdx.x & 31;
    if (warp >= kNTOT) return;
    const float* tn = t + (long)warp * kTC;
    const float* w0 = fcw;
    const float* w1 = fcw + 512;
    float s0 = 0.f, s1 = 0.f, r0 = 0.f, r1 = 0.f;
#pragma unroll
    for (int q = 0; q < 8; q++) {
        int d = lane + 32 * q;
        float u = fmaxf(tn[d], 0.f);
        s0 += u * w0[d];       s1 += u * w1[d];
        r0 += u * w0[256 + d]; r1 += u * w1[256 + d];
    }
#pragma unroll
    for (int off = 16; off; off >>= 1) {
        s0 += __shfl_down_sync(0xffffffffu, s0, off);
        s1 += __shfl_down_sync(0xffffffffu, s1, off);
        r0 += __shfl_down_sync(0xffffffffu, r0, off);
        r1 += __shfl_down_sync(0xffffffffu, r1, off);
    }
    if (lane == 0) {
        Eg[warp] = expf(r1 - r0 + fcb[1] - fcb[0]);
        Fg[warp] = expf(s1 - s0);
    }
}

__global__ void k_buildA(const float* __restrict__ gu,
                         const float* __restrict__ Eg, const float* __restrict__ Fg,
                         unsigned char* __restrict__ A8) {
    int idx = blockIdx.x * 256 + threadIdx.x;
    int j0 = (idx & 127) << 2;
    int i  = (idx >> 7) & 511;
    int b  = idx >> 16;
    float Ei = Eg[b * kN + i];
    float4 Fv = *reinterpret_cast<const float4*>(Fg + b * kN + j0);
    const float4* g4 = reinterpret_cast<const float4*>(
        gu + ((long)(b * kN + i) * kN + j0) * 2);
    float4 u01 = g4[0];
    float4 u23 = g4[1];
    auto bit = [&](float ux, float uy, float Fj) -> unsigned char {
        ux = fminf(fmaxf(ux, 1e-9f), 1.0f - 1e-9f);
        uy = fminf(fmaxf(uy, 1e-9f), 1.0f - 1e-9f);
        float l0 = -__logf(ux);
        float l1 = -__logf(uy);
        return (l1 >= l0 * Ei * Fj) ? 1 : 0;
    };
    uchar4 r;
    r.x = bit(u01.x, u01.y, Fv.x);
    r.y = bit(u01.z, u01.w, Fv.y);
    r.z = bit(u23.x, u23.y, Fv.z);
    r.w = bit(u23.z, u23.w, Fv.w);
    *reinterpret_cast<uchar4*>(A8 + (long)(b * kN + i) * kN + j0) = r;
}

__global__ void k_colsum_part(const unsigned char* __restrict__ A8,
                              float* __restrict__ part) {
    int b = blockIdx.x;
    int j = threadIdx.x;
    int r0 = blockIdx.y * 64;
    const unsigned char* Ab = A8 + (long)b * kN * kN;
    int s = 0;
#pragma unroll 8
    for (int r = r0; r < r0 + 64; r++) s += Ab[(long)r * kN + j];
    part[((long)b * 8 + blockIdx.y) * kN + j] = (float)s;
}

__global__ void k_disD(const float* __restrict__ part, float* __restrict__ disD) {
    int i = blockIdx.x * 256 + threadIdx.x;
    if (i >= kNTOT) return;
    int b = i >> 9, j = i & 511;
    float s = 1.f;
#pragma unroll
    for (int c = 0; c < 8; c++) s += part[((long)b * 8 + c) * kN + j];
    disD[i] = rsqrtf(s);
}

__global__ void k_degS(const int* __restrict__ colp, int* degS) {
    int e = blockIdx.x * 256 + threadIdx.x;
    if (e < kE) atomicAdd(&degS[colp[e]], 1);
}

__global__ void k_disS(const int* __restrict__ degS, float* __restrict__ disS) {
    int i = blockIdx.x * 256 + threadIdx.x;
    if (i < kNTOT) disS[i] = rsqrtf((float)degS[i] + 1.f);
}

__global__ void k_scan(const int* __restrict__ degS, int* __restrict__ ns,
                       int* __restrict__ cur) {
    __shared__ int sm[1024];
    int tid = threadIdx.x;
    int base = tid * 16;
    int local[16];
    int sum = 0;
#pragma unroll
    for (int v = 0; v < 16; v++) { local[v] = degS[base + v]; sum += local[v]; }
    sm[tid] = sum;
    __syncthreads();
    for (int off = 1; off < 1024; off <<= 1) {
        int v = (tid >= off) ? sm[tid - off] : 0;
        __syncthreads();
        sm[tid] += v;
        __syncthreads();
    }
    int run = sm[tid] - sum;
#pragma unroll
    for (int v = 0; v < 16; v++) {
        ns[base + v] = run;
        cur[base + v] = run;
        run += local[v];
    }
    if (tid == 1023) ns[kNTOT] = run;
}

__global__ void k_fill(const int* __restrict__ rowp, const int* __restrict__ colp,
                       int* cur, int* __restrict__ esrc) {
    int e = blockIdx.x * 256 + threadIdx.x;
    if (e < kE) {
        int c = colp[e];
        int p = atomicAdd(&cur[c], 1);
        esrc[p] = rowp[e];
    }
}

// ---------------------------------------------------------------------------
// fp16 CSR gather: WPN warps per node, VH half2 per lane.
// ---------------------------------------------------------------------------
template <int WPN, int VH>
__global__ __launch_bounds__(256) void k_gather_h(
        const int* __restrict__ ns, const int* __restrict__ esrc,
        const __half2* __restrict__ xwh, const float* __restrict__ disS,
        const float* __restrict__ bias, float* __restrict__ out,
        int outStride, int outOffset) {
    constexpr int F2 = WPN * VH * 32;
    int gw = (blockIdx.x * 256 + threadIdx.x) >> 5;
    int lane = threadIdx.x & 31;
    int node = gw / WPN;
    int part = gw % WPN;
    if (node >= kNTOT) return;
    int off2 = (part * 32 + lane) * VH;
    float dc = disS[node];
    float2 acc[VH];

    auto loadrow = [&](long r, uint32_t* rw) {
        const char* p = reinterpret_cast<const char*>(xwh + r * F2 + off2);
        if (VH == 4) {
            uint4 u = *reinterpret_cast<const uint4*>(p);
            rw[0] = u.x; rw[1] = u.y; rw[2] = u.z; rw[3] = u.w;
        } else {
            uint2 u = *reinterpret_cast<const uint2*>(p);
            rw[0] = u.x; rw[1] = u.y;
        }
    };

    {
        uint32_t rw[VH];
        loadrow(node, rw);
        float d2 = dc * dc;
#pragma unroll
        for (int v = 0; v < VH; v++) {
            float2 xv = __half22float2(*reinterpret_cast<__half2*>(&rw[v]));
            float2 bb = *reinterpret_cast<const float2*>(bias + (off2 + v) * 2);
            acc[v] = make_float2(xv.x * d2 + bb.x, xv.y * d2 + bb.y);
        }
    }
    int s = ns[node], e = ns[node + 1];
    int i = s;
    for (; i + 8 <= e; i += 8) {
        int r[8];
        float sc[8];
        uint32_t rw[8][VH];
#pragma unroll
        for (int q = 0; q < 8; q++) r[q] = esrc[i + q];
#pragma unroll
        for (int q = 0; q < 8; q++) sc[q] = disS[r[q]] * dc;
#pragma unroll
        for (int q = 0; q < 8; q++) loadrow(r[q], rw[q]);
#pragma unroll
        for (int q = 0; q < 8; q++)
#pragma unroll
            for (int v = 0; v < VH; v++) {
                float2 xv = __half22float2(*reinterpret_cast<__half2*>(&rw[q][v]));
                acc[v].x += xv.x * sc[q];
                acc[v].y += xv.y * sc[q];
            }
    }
    for (; i < e; i++) {
        int r = esrc[i];
        float sr = disS[r] * dc;
        uint32_t rw[VH];
        loadrow(r, rw);
#pragma unroll
        for (int v = 0; v < VH; v++) {
            float2 xv = __half22float2(*reinterpret_cast<__half2*>(&rw[v]));
            acc[v].x += xv.x * sr;
            acc[v].y += xv.y * sr;
        }
    }
    float* op = out + (long)node * outStride + outOffset + off2 * 2;
#pragma unroll
    for (int v = 0; v < VH; v++)
        *reinterpret_cast<float2*>(op + v * 2) = acc[v];
}

// ---------------------------------------------------------------------------
// tf32 NT GEMM (R13-proven), ldmatrix fragment loads; fp32/fp16 outputs.
// ---------------------------------------------------------------------------
template <bool RELU_A>
__global__ __launch_bounds__(256) void k_gemm_tf32(
        const float* __restrict__ A,
        const float* __restrict__ B,
        float* __restrict__ C,
        int Nf, int K, __half* __restrict__ Ch) {
    __shared__ uint32_t As[2][128][20];
    __shared__ uint32_t Bs[2][128][20];
    int m0 = blockIdx.y * 128, n0 = blockIdx.x * 128;
    int t = threadIdx.x;
    int wid = t >> 5, lane = t & 31;
    int mw = (wid >> 1) * 32, nw = (wid & 1) * 64;
    int g = lane >> 2, tg = lane & 3;
    int lrow16 = lane & 15;
    int lhalf4 = (lane >> 4) * 4;
    int lr = t >> 2, lc = (t & 3) << 2;

    uint32_t sA[2] = { smem_u32(&As[0][0][0]), smem_u32(&As[1][0][0]) };
    uint32_t sB[2] = { smem_u32(&Bs[0][0][0]), smem_u32(&Bs[1][0][0]) };

    float acc[2][8][4];
#pragma unroll
    for (int i = 0; i < 2; i++)
#pragma unroll
        for (int j = 0; j < 8; j++)
#pragma unroll
            for (int c = 0; c < 4; c++) acc[i][j][c] = 0.f;

    const float* aP0 = A + (long)(m0 + lr) * K + lc;
    const float* aP1 = A + (long)(m0 + lr + 64) * K + lc;
    const float* bP0 = B + (long)(n0 + lr) * K + lc;
    const float* bP1 = B + (long)(n0 + lr + 64) * K + lc;

    auto cvt4 = [](float4 v, bool relu) -> uint4 {
        if (relu) {
            v.x = fmaxf(v.x, 0.f); v.y = fmaxf(v.y, 0.f);
            v.z = fmaxf(v.z, 0.f); v.w = fmaxf(v.w, 0.f);
        }
        uint4 r;
        r.x = f2tf(v.x); r.y = f2tf(v.y); r.z = f2tf(v.z); r.w = f2tf(v.w);
        return r;
    };

    {
        uint4 a0 = cvt4(*reinterpret_cast<const float4*>(aP0), RELU_A);
        uint4 a1 = cvt4(*reinterpret_cast<const float4*>(aP1), RELU_A);
        uint4 b0 = cvt4(*reinterpret_cast<const float4*>(bP0), false);
        uint4 b1 = cvt4(*reinterpret_cast<const float4*>(bP1), false);
        *reinterpret_cast<uint4*>(&As[0][lr][lc]) = a0;
        *reinterpret_cast<uint4*>(&As[0][lr + 64][lc]) = a1;
        *reinterpret_cast<uint4*>(&Bs[0][lr][lc]) = b0;
        *reinterpret_cast<uint4*>(&Bs[0][lr + 64][lc]) = b1;
    }
    __syncthreads();

    int buf = 0;
    for (int k0 = 0; k0 < K; k0 += 16) {
        bool more = (k0 + 16) < K;
        float4 na0, na1, nb0, nb1;
        if (more) {
            na0 = *reinterpret_cast<const float4*>(aP0 + k0 + 16);
            na1 = *reinterpret_cast<const float4*>(aP1 + k0 + 16);
            nb0 = *reinterpret_cast<const float4*>(bP0 + k0 + 16);
            nb1 = *reinterpret_cast<const float4*>(bP1 + k0 + 16);
        }
#pragma unroll
        for (int s = 0; s < 2; s++) {
            int kcol = s * 8 + lhalf4;
            uint32_t af0[4], af1[4];
            ldsm4(af0, sA[buf] + ((mw + lrow16) * 20 + kcol) * 4);
            ldsm4(af1, sA[buf] + ((mw + 16 + lrow16) * 20 + kcol) * 4);
#pragma unroll
            for (int p = 0; p < 4; p++) {
                uint32_t bf[4];
                ldsm4(bf, sB[buf] + ((nw + p * 16 + lrow16) * 20 + kcol) * 4);
                mma_tf32(acc[0][2 * p],     af0, bf[0], bf[2]);
                mma_tf32(acc[0][2 * p + 1], af0, bf[1], bf[3]);
                mma_tf32(acc[1][2 * p],     af1, bf[0], bf[2]);
                mma_tf32(acc[1][2 * p + 1], af1, bf[1], bf[3]);
            }
        }
        if (more) {
            int nb = buf ^ 1;
            *reinterpret_cast<uint4*>(&As[nb][lr][lc]) = cvt4(na0, RELU_A);
            *reinterpret_cast<uint4*>(&As[nb][lr + 64][lc]) = cvt4(na1, RELU_A);
            *reinterpret_cast<uint4*>(&Bs[nb][lr][lc]) = cvt4(nb0, false);
            *reinterpret_cast<uint4*>(&Bs[nb][lr + 64][lc]) = cvt4(nb1, false);
            __syncthreads();
            buf = nb;
        }
    }

#pragma unroll
    for (int mt = 0; mt < 2; mt++) {
        int row = m0 + mw + mt * 16 + g;
#pragma unroll
        for (int j = 0; j < 8; j++) {
            int col = n0 + nw + j * 8 + 2 * tg;
            float2 v0 = make_float2(acc[mt][j][0], acc[mt][j][1]);
            float2 v1 = make_float2(acc[mt][j][2], acc[mt][j][3]);
            if (C) {
                *reinterpret_cast<float2*>(C + (long)row * Nf + col) = v0;
                *reinterpret_cast<float2*>(C + (long)(row + 8) * Nf + col) = v1;
            }
            if (Ch) {
                *reinterpret_cast<__half2*>(Ch + (long)row * Nf + col) =
                    __floats2half2_rn(v0.x, v0.y);
                *reinterpret_cast<__half2*>(Ch + (long)(row + 8) * Nf + col) =
                    __floats2half2_rn(v1.x, v1.y);
            }
        }
    }
}

// ---------------------------------------------------------------------------
// fp16 HMMA dense GCN propagation (m16n8k16, fp32 accum) — R13-proven
// ---------------------------------------------------------------------------
template <bool RELU, bool XHALF>
__global__ __launch_bounds__(256) void k_prop_h(
        const unsigned char* __restrict__ Adj8, const void* __restrict__ XWv,
        const float* __restrict__ dis, const float* __restrict__ bias,
        float* __restrict__ out, int F, int outStride, int outOffset) {
    __shared__ __half As[2][16][136];
    __shared__ __half Bs[2][16][136];
    int b = blockIdx.z;
    const unsigned char* Ab = Adj8 + (long)b * kN * kN;
    const float* Xf = XHALF ? nullptr : (const float*)XWv + (long)b * kN * F;
    const __half* Xh = XHALF ? (const __half*)XWv + (long)b * kN * F : nullptr;
    const float* db = dis + b * kN;
    float* Ob = out + (long)b * kN * outStride + outOffset;
    int i0 = blockIdx.y * 128, f0 = blockIdx.x * 128;
    int t = threadIdx.x;
    int wid = t >> 5, lane = t & 31;
    int mw = (wid >> 1) * 32, nw = (wid & 1) * 64;
    int g = lane >> 2, tg = lane & 3;
    int jj = t >> 4;
    int ii = (t & 15) << 3;

    int l8 = lane & 7;
    int gA_k = (lane >> 4) * 8 + l8;
    int gA_m = ((lane >> 3) & 1) * 8;
    int gB_k = ((lane >> 3) & 1) * 8 + l8;
    int gB_n = (lane >> 4) * 8;

    uint32_t sAb[2] = { smem_u32(&As[0][0][0]), smem_u32(&As[1][0][0]) };
    uint32_t sBb[2] = { smem_u32(&Bs[0][0][0]), smem_u32(&Bs[1][0][0]) };

    float acc[2][8][4];
#pragma unroll
    for (int i = 0; i < 2; i++)
#pragma unroll
        for (int j = 0; j < 8; j++)
#pragma unroll
            for (int c = 0; c < 4; c++) acc[i][j][c] = 0.f;

    auto ldX8 = [&](int row, float* xv) {
        if (XHALF) {
            uint4 raw = *reinterpret_cast<const uint4*>(Xh + (long)row * F + f0 + ii);
            const __half2* hp = reinterpret_cast<const __half2*>(&raw);
#pragma unroll
            for (int v = 0; v < 4; v++) {
                float2 f = __half22float2(hp[v]);
                xv[2 * v] = f.x; xv[2 * v + 1] = f.y;
            }
        } else {
            *reinterpret_cast<float4*>(xv) =
                *reinterpret_cast<const float4*>(Xf + (long)row * F + f0 + ii);
            *reinterpret_cast<float4*>(xv + 4) =
                *reinterpret_cast<const float4*>(Xf + (long)row * F + f0 + ii + 4);
        }
    };

    auto hb = [](uint32_t byte) -> uint32_t { return byte ? 0x3C00u : 0u; };

    auto stTile = [&](int bufI, uint2 rawA, const float* xv, float dj) {
        uint4 ua;
        ua.x = hb(rawA.x & 0xffu)         | (hb((rawA.x >> 8) & 0xffu) << 16);
        ua.y = hb((rawA.x >> 16) & 0xffu) | (hb(rawA.x >> 24) << 16);
        ua.z = hb(rawA.y & 0xffu)         | (hb((rawA.y >> 8) & 0xffu) << 16);
        ua.w = hb((rawA.y >> 16) & 0xffu) | (hb(rawA.y >> 24) << 16);
        uint4 ub;
        ub.x = h2u(__floats2half2_rn(xv[0] * dj, xv[1] * dj));
        ub.y = h2u(__floats2half2_rn(xv[2] * dj, xv[3] * dj));
        ub.z = h2u(__floats2half2_rn(xv[4] * dj, xv[5] * dj));
        ub.w = h2u(__floats2half2_rn(xv[6] * dj, xv[7] * dj));
        *reinterpret_cast<uint4*>(&As[bufI][jj][ii]) = ua;
        *reinterpret_cast<uint4*>(&Bs[bufI][jj][ii]) = ub;
    };

    {
        uint2 rawA = *reinterpret_cast<const uint2*>(Ab + (long)jj * kN + i0 + ii);
        float xv[8];
        ldX8(jj, xv);
        stTile(0, rawA, xv, db[jj]);
    }
    __syncthreads();

    int buf = 0;
    for (int j0 = 0; j0 < kN; j0 += 16) {
        bool more = (j0 + 16) < kN;
        uint2 nraw;
        float nxv[8];
        float djn = 0.f;
        if (more) {
            nraw = *reinterpret_cast<const uint2*>(
                Ab + (long)(j0 + 16 + jj) * kN + i0 + ii);
            ldX8(j0 + 16 + jj, nxv);
            djn = db[j0 + 16 + jj];
        }
        {
            uint32_t a0[4], a1[4];
            ldsm4t(a0, sAb[buf] + (gA_k * 136 + mw + gA_m) * 2);
            ldsm4t(a1, sAb[buf] + (gA_k * 136 + mw + 16 + gA_m) * 2);
#pragma unroll
            for (int p = 0; p < 4; p++) {
                uint32_t bf[4];
                ldsm4t(bf, sBb[buf] + (gB_k * 136 + nw + p * 16 + gB_n) * 2);
                mma_f16(acc[0][2 * p],     a0, bf[0], bf[1]);
                mma_f16(acc[0][2 * p + 1], a0, bf[2], bf[3]);
                mma_f16(acc[1][2 * p],     a1, bf[0], bf[1]);
                mma_f16(acc[1][2 * p + 1], a1, bf[2], bf[3]);
            }
        }
        if (more) {
            int nb = buf ^ 1;
            stTile(nb, nraw, nxv, djn);
            __syncthreads();
            buf = nb;
        }
    }

#pragma unroll
    for (int mt = 0; mt < 2; mt++) {
        int rowA = i0 + mw + mt * 16 + g;
        float diA = db[rowA], diB = db[rowA + 8];
#pragma unroll
        for (int j = 0; j < 8; j++) {
            int col = f0 + nw + j * 8 + 2 * tg;
            float2 bb = *reinterpret_cast<const float2*>(bias + col);
            float2 xA, xB;
            if (XHALF) {
                xA = __half22float2(*reinterpret_cast<const __half2*>(
                    Xh + (long)rowA * F + col));
                xB = __half22float2(*reinterpret_cast<const __half2*>(
                    Xh + (long)(rowA + 8) * F + col));
            } else {
                xA = *reinterpret_cast<const float2*>(Xf + (long)rowA * F + col);
                xB = *reinterpret_cast<const float2*>(Xf + (long)(rowA + 8) * F + col);
            }
            float v0 = diA * (acc[mt][j][0] + diA * xA.x) + bb.x;
            float v1 = diA * (acc[mt][j][1] + diA * xA.y) + bb.y;
            float v2 = diB * (acc[mt][j][2] + diB * xB.x) + bb.x;
            float v3 = diB * (acc[mt][j][3] + diB * xB.y) + bb.y;
            if (RELU) {
                v0 = fmaxf(v0, 0.f); v1 = fmaxf(v1, 0.f);
                v2 = fmaxf(v2, 0.f); v3 = fmaxf(v3, 0.f);
            }
            *reinterpret_cast<float2*>(Ob + (long)rowA * outStride + col) =
                make_float2(v0, v1);
            *reinterpret_cast<float2*>(Ob + (long)(rowA + 8) * outStride + col) =
                make_float2(v2, v3);
        }
    }
}

// ---------------------------------------------------------------------------
// fcn1 half (strided k-half), double-buffered
// ---------------------------------------------------------------------------
__global__ void k_fcn1_half(const float* __restrict__ emb, const float* __restrict__ W,
                            float* __restrict__ h1, int colOff) {
    constexpr int KH = kKTOT / 2;
    constexpr int KC = KH / 64;     // 1024
    __shared__ float As[16][32];
    __shared__ float Bs[16][64];
    int n0 = blockIdx.x * 64;
    int kbase = blockIdx.y * KC;
    int t = threadIdx.x;
    int m = t & 31;
    int nb = (t >> 5) << 3;
    int row = t >> 2, c4 = (t & 3) << 2;
    float acc[8];
#pragma unroll
    for (int j = 0; j < 8; j++) acc[j] = 0.f;

    auto kmap = [&](int k) -> long {
        return ((long)(k >> 7) << 8) + colOff + (k & 127);
    };

    float4 aPre, bPre;
    if (t < 128)
        aPre = *reinterpret_cast<const float4*>(emb + (long)row * kKTOT + kmap(kbase + c4));
    bPre = *reinterpret_cast<const float4*>(W + (long)(n0 + row) * kKTOT + kmap(kbase + c4));

    for (int k0 = kbase; k0 < kbase + KC; k0 += 16) {
        if (t < 128) {
            As[c4 + 0][row] = aPre.x; As[c4 + 1][row] = aPre.y;
            As[c4 + 2][row] = aPre.z; As[c4 + 3][row] = aPre.w;
        }
        Bs[c4 + 0][row] = bPre.x; Bs[c4 + 1][row] = bPre.y;
        Bs[c4 + 2][row] = bPre.z; Bs[c4 + 3][row] = bPre.w;
        __syncthreads();
        bool more = (k0 + 16) < kbase + KC;
        if (more) {
            if (t < 128)
                aPre = *reinterpret_cast<const float4*>(
                    emb + (long)row * kKTOT + kmap(k0 + 16 + c4));
            bPre = *reinterpret_cast<const float4*>(
                W + (long)(n0 + row) * kKTOT + kmap(k0 + 16 + c4));
        }
#pragma unroll
        for (int k = 0; k < 16; k++) {
            float a = As[k][m];
#pragma unroll
            for (int j = 0; j < 8; j++) acc[j] += a * Bs[k][nb + j];
        }
        __syncthreads();
    }
#pragma unroll
    for (int j = 0; j < 8; j++)
        atomicAdd(&h1[m * 256 + n0 + nb + j], acc[j]);
}

__global__ void k_fcn23(const float* __restrict__ h1g,
                        const float* __restrict__ b1, const float* __restrict__ w2,
                        const float* __restrict__ b2, const float* __restrict__ w3,
                        const float* __restrict__ b3, float* __restrict__ out) {
    __shared__ float h1s[32][256];
    __shared__ float h2s[32][32];
    int t = threadIdx.x;
    for (int idx = t; idx < 32 * 256; idx += 1024) {
        float v = h1g[idx] + b1[idx & 255];
        h1s[idx >> 8][idx & 255] = (v >= 0.f) ? v : 0.2f * v;
    }
    __syncthreads();
    {
        int b = t >> 5, o = t & 31;
        float s = 0.f;
#pragma unroll 8
        for (int k = 0; k < 256; k++) s += h1s[b][k] * w2[o * 256 + k];
        s += b2[o];
        h2s[b][o] = (s >= 0.f) ? s : 0.2f * s;
    }
    __syncthreads();
    if (t < 64) {
        int b = t >> 1, o = t & 1;
        float s = 0.f;
#pragma unroll
        for (int k = 0; k < 32; k++) s += h2s[b][k] * w3[o * 32 + k];
        out[b * 2 + o] = s + b3[o];
    }
}

// ---------------------------------------------------------------------------
// Launch
// ---------------------------------------------------------------------------
extern "C" void kernel_launch(void* const* d_in, const int* in_sizes, int n_in,
                              void* d_out, int out_size) {
    const float* x    = (const float*)d_in[0];
    const float* t    = (const float*)d_in[1];
    const float* gu   = (const float*)d_in[2];
    const int*   ei   = (const int*)d_in[3];
    const float* w1   = (const float*)d_in[4];
    const float* b1   = (const float*)d_in[5];
    const float* w2   = (const float*)d_in[6];
    const float* b2   = (const float*)d_in[7];
    const float* fcw  = (const float*)d_in[8];
    const float* fcb  = (const float*)d_in[9];
    const float* f1w  = (const float*)d_in[10];
    const float* f1b  = (const float*)d_in[11];
    const float* f2w  = (const float*)d_in[12];
    const float* f2b  = (const float*)d_in[13];
    const float* f3w  = (const float*)d_in[14];
    const float* f3b  = (const float*)d_in[15];
    float* out = (float*)d_out;

    const int* rowp = ei;
    const int* colp = ei + kE;

    float* base = nullptr;
    cudaGetSymbolAddress((void**)&base, g_scratch);
    float* p_E     = base + OFF_EG;
    float* p_F     = base + OFF_FG;
    unsigned char* p_A8 = (unsigned char*)(base + OFF_A8);
    float* p_disD  = base + OFF_DISD;
    float* p_part  = base + OFF_PART;
    float* p_h     = base + OFF_H;
    float* p_sc1   = base + OFF_SC1;
    float* p_emb   = base + OFF_EMB;
    float* p_disS  = base + OFF_DISS;
    int*   p_degS  = (int*)(base + OFF_DEGS);
    float* p_h1    = base + OFF_H1;
    int*   p_ns    = (int*)(base + OFF_NS);
    int*   p_cur   = (int*)(base + OFF_CUR);
    int*   p_esrc  = (int*)(base + OFF_ESRC);
    __half* p_xw1h  = (__half*)(base + OFF_XW1H);
    __half* p_xw2h  = (__half*)(base + OFF_XW2H);
    __half* p_xws2h = (__half*)(base + OFF_XWS2H);

    static cudaStream_t sG = nullptr, sC = nullptr;
    static cudaEvent_t evStart, evZ, evG1, evCSR, evF1s;
    if (!sG) {
        cudaStreamCreateWithFlags(&sG, cudaStreamNonBlocking);
        cudaStreamCreateWithFlags(&sC, cudaStreamNonBlocking);
        cudaEventCreateWithFlags(&evStart, cudaEventDisableTiming);
        cudaEventCreateWithFlags(&evZ, cudaEventDisableTiming);
        cudaEventCreateWithFlags(&evG1, cudaEventDisableTiming);
        cudaEventCreateWithFlags(&evCSR, cudaEventDisableTiming);
        cudaEventCreateWithFlags(&evF1s, cudaEventDisableTiming);
    }

    cudaEventRecord(evStart, 0);
    cudaStreamWaitEvent(sG, evStart, 0);
    cudaStreamWaitEvent(sC, evStart, 0);

    // main: zero + dense prep
    k_zeroS<<<64, 256>>>(p_degS, p_h1);
    cudaEventRecord(evZ, 0);
    k_lslr<<<kNTOT / 8, 256>>>(t, fcw, fcb, p_E, p_F);
    k_buildA<<<kBZ * kN * kN / 1024, 256>>>(gu, p_E, p_F, p_A8);

    // sG: gemm1 — fp16 output only (captured slot)
    k_gemm_tf32<false><<<dim3(kF1 / 128, kNTOT / 128, 1), 256, 0, sG>>>(
        x, w1, nullptr, kF1, kN, p_xw1h);
    cudaEventRecord(evG1, sG);

    // main: dense degrees (atomic-free)
    k_colsum_part<<<dim3(kBZ, 8), kN>>>(p_A8, p_part);
    k_disD<<<kNTOT / 256, 256>>>(p_part, p_disD);

    // sC: CSR chain
    cudaStreamWaitEvent(sC, evZ, 0);
    k_degS<<<kE / 256, 256, 0, sC>>>(colp, p_degS);
    k_disS<<<kNTOT / 256, 256, 0, sC>>>(p_degS, p_disS);
    k_scan<<<1, 1024, 0, sC>>>(p_degS, p_ns, p_cur);
    k_fill<<<kE / 256, 256, 0, sC>>>(rowp, colp, p_cur, p_esrc);
    cudaEventRecord(evCSR, sC);

    // ===== dense pipeline (main) =====
    cudaStreamWaitEvent(0, evG1, 0);
    k_prop_h<true, true><<<dim3(kF1 / 128, kN / 128, kBZ), 256>>>(
        p_A8, p_xw1h, p_disD, b1, p_h, kF1, kF1, 0);
    k_gemm_tf32<true><<<dim3(kF2 / 128, kNTOT / 128, 1), 256>>>(
        p_h, w2, nullptr, kF2, kF1, p_xw2h);
    k_prop_h<false, true><<<dim3(kF2 / 128, kN / 128, kBZ), 256>>>(
        p_A8, p_xw2h, p_disD, b2, p_emb, kF2, 256, 0);
    k_fcn1_half<<<dim3(4, 64), 256>>>(p_emb, f1w, p_h1, 0);

    // ===== sparse pipeline (sG) =====
    cudaStreamWaitEvent(sG, evCSR, 0);
    k_gather_h<2, 2><<<kNTOT * 2 / 8, 256, 0, sG>>>(p_ns, p_esrc,
        (const __half2*)p_xw1h, p_disS, b1, p_sc1, kF1, 0);
    k_gemm_tf32<true><<<dim3(kF2 / 128, kNTOT / 128, 1), 256, 0, sG>>>(
        p_sc1, w2, nullptr, kF2, kF1, p_xws2h);
    k_gather_h<1, 2><<<kNTOT / 8, 256, 0, sG>>>(p_ns, p_esrc,
        (const __half2*)p_xws2h, p_disS, b2, p_emb, 256, 128);
    k_fcn1_half<<<dim3(4, 64), 256, 0, sG>>>(p_emb, f1w, p_h1, 128);
    cudaEventRecord(evF1s, sG);

    // join + head
    cudaStreamWaitEvent(0, evF1s, 0);
    k_fcn23<<<1, 1024>>>(p_h1, f1b, f2w, f2b, f3w, f3b, out);
}